// round 15
// baseline (speedup 1.0000x reference)
#include <cuda_runtime.h>
#include <cuda_bf16.h>
#include <math.h>
#include <stdint.h>

#define NB 8
#define NS 2048
#define ND 256
#define NE 256
static constexpr float kScale = 0.125f;  // 1/sqrt(64), per reference source

typedef unsigned long long u64;
typedef uint32_t u32;
typedef unsigned short u16;

// ---------------- cp.async ----------------
__device__ __forceinline__ void cp16(u32 smem_dst, const void* gmem_src) {
    asm volatile("cp.async.cg.shared.global [%0], [%1], 16;" :: "r"(smem_dst), "l"(gmem_src));
}
__device__ __forceinline__ void cp_commit() {
    asm volatile("cp.async.commit_group;" ::: "memory");
}
__device__ __forceinline__ void cp_wait0() { asm volatile("cp.async.wait_group 0;" ::: "memory"); }
__device__ __forceinline__ void cp_wait1() { asm volatile("cp.async.wait_group 1;" ::: "memory"); }

// ---------------- mma.sync / ldmatrix (family-wide, works on sm_103) ----------
__device__ __forceinline__ void ldsm4(u32* d, u32 addr) {
    asm volatile("ldmatrix.sync.aligned.m8n8.x4.shared.b16 {%0,%1,%2,%3}, [%4];"
        : "=r"(d[0]), "=r"(d[1]), "=r"(d[2]), "=r"(d[3]) : "r"(addr));
}
__device__ __forceinline__ void mma_bf16(float* c, const u32* a, u32 b0, u32 b1) {
    asm volatile("mma.sync.aligned.m16n8k16.row.col.f32.bf16.bf16.f32 "
        "{%0,%1,%2,%3}, {%4,%5,%6,%7}, {%8,%9}, {%0,%1,%2,%3};"
        : "+f"(c[0]), "+f"(c[1]), "+f"(c[2]), "+f"(c[3])
        : "r"(a[0]), "r"(a[1]), "r"(a[2]), "r"(a[3]), "r"(b0), "r"(b1));
}

// ---------------- shared helpers ----------------
__device__ __forceinline__ u32 swz(u32 o) { return o ^ ((o >> 3) & 0x70); }
// 64-row x 512B image in 1KB atoms (8 rows x 128B), atom = (r>>3) + (cb>>7)*8
__device__ __forceinline__ u32 off64(int r, int cb) {
    return swz((u32)(((r >> 3) + (cb >> 7) * 8) * 1024 + (r & 7) * 128 + (cb & 127)));
}
// 128B-row image (Vt: 256 rows, P: 64 rows)
__device__ __forceinline__ u32 off128(int r, int cb) {
    return swz((u32)(r * 128 + cb));
}
// A-fragment (m16k16): reg g -> rows r0+8*(g&1), col cb+16*(g>>1)
__device__ __forceinline__ void lda(u32* d, u32 base, int r0, int cb, int lane, bool wide) {
    int g = lane >> 3;
    int r = r0 + (lane & 7) + (g & 1) * 8;
    int c = cb + (g >> 1) * 16;
    ldsm4(d, base + (wide ? off64(r, c) : off128(r, c)));
}
// B-fragments for two n-tiles: reg g -> rows n0+8*(g>>1), col cb+16*(g&1)
__device__ __forceinline__ void ldb(u32* d, u32 base, int n0, int cb, int lane, bool wide) {
    int g = lane >> 3;
    int r = n0 + (lane & 7) + (g >> 1) * 8;
    int c = cb + (g & 1) * 16;
    ldsm4(d, base + (wide ? off64(r, c) : off128(r, c)));
}

__device__ __forceinline__ void packsplit(float x, float y, u32& hi, u32& lo) {
    __nv_bfloat16 xh = __float2bfloat16_rn(x), yh = __float2bfloat16_rn(y);
    __nv_bfloat16 xl = __float2bfloat16_rn(x - __bfloat162float(xh));
    __nv_bfloat16 yl = __float2bfloat16_rn(y - __bfloat162float(yh));
    hi = (u32)__bfloat16_as_ushort(xh) | ((u32)__bfloat16_as_ushort(yh) << 16);
    lo = (u32)__bfloat16_as_ushort(xl) | ((u32)__bfloat16_as_ushort(yl) << 16);
}

// ---------------- global bf16 scratch ----------------
__device__ __align__(16) __nv_bfloat16 gQh[NB * NS * NE];
__device__ __align__(16) __nv_bfloat16 gQl[NB * NS * NE];
__device__ __align__(16) __nv_bfloat16 gKh[NB * NS * NE];
__device__ __align__(16) __nv_bfloat16 gKl[NB * NS * NE];
__device__ __align__(16) __nv_bfloat16 gVth[NB * NE * NS];
__device__ __align__(16) __nv_bfloat16 gVtl[NB * NE * NS];

// ---------------------------------------------------------------------------
// Prep v5: tensor-core QKV projection; pipelined W stream (raw smem buffer)
// AND smem-staged epilogue — fragments scatter bf16 hi/lo into a [64][64]
// staging tile in DESTINATION orientation, then all threads store 128B rows
// coalesced (4 sectors/row instead of 32 scattered sectors per STG).
// ---------------------------------------------------------------------------
#define PXH  0
#define PXL  32768
#define PWH  65536
#define PWL  98304
#define PRAW 131072           // 256 d-rows x 256B raw fp32 W chunk (64KB)
#define PSH  196608           // staging hi: [64][64] bf16 (8KB)
#define PSL  204800           // staging lo: [64][64] bf16 (8KB)
#define PTOT 212992

__global__ __launch_bounds__(512, 1) void qkv_prep5(const float* __restrict__ x,
                                                    const float* __restrict__ w) {
    extern __shared__ __align__(1024) char smc[];
    const u32 sm = (u32)__cvta_generic_to_shared(smc);
    const int rows0 = blockIdx.x * 64;
    const int b = rows0 >> 11;                 // batch
    const int key0 = rows0 & (NS - 1);         // key base within batch
    const int tid = threadIdx.x, lane = tid & 31, wid = tid >> 5;
    const int wq = wid & 3, wn = wid >> 2;
    const int r0 = wq * 16, n0 = wn * 16;
    const int rl = r0 + (lane >> 2), rh = rl + 8;   // block-local rows (q or key)
    const int c0 = n0 + 2 * (lane & 3);             // output col within 64-chunk

    // ---- raw W(0) prefetch (cp.async, overlaps the X fill below) ----
    for (int i = tid; i < 4096; i += 512) {
        int d = i >> 4, seg = (i & 15) << 4;
        cp16(sm + PRAW + d * 256 + seg, (const char*)w + (size_t)d * NE * 4 + seg);
    }
    cp_commit();

    // ---- X tile 64x256 fp32 -> Xh/Xl images, ONCE ----
    for (int i = tid; i < 4096; i += 512) {
        int r = i >> 6, d0 = (i & 63) << 2;
        float4 v = *(const float4*)&x[(size_t)(rows0 + r) * ND + d0];
        u32 h0, l0, h1, l1;
        packsplit(v.x, v.y, h0, l0);
        packsplit(v.z, v.w, h1, l1);
        u32 o = off64(r, d0 * 2);
        *(uint2*)(smc + PXH + o) = make_uint2(h0, h1);
        *(uint2*)(smc + PXL + o) = make_uint2(l0, l1);
    }

    // ---- 12 chunks: p = chunk/4 (projection), col0 = (chunk%4)*64 ----
    for (int ch = 0; ch < 12; ch++) {
        const int p = ch >> 2;
        const int col0 = (ch & 3) << 6;

        cp_wait0();        // raw W(ch) resident (thread-local)
        __syncthreads();   // raw visible; staging from prev chunk fully drained

        // Convert raw -> W hi/lo images (row = e local, col = d), LDS+STS only.
        for (int i = tid; i < 2048; i += 512) {
            int d2 = i >> 4;
            int eg = (i & 15) << 2;
            float4 va = *(const float4*)(smc + PRAW + (2 * d2) * 256 + eg * 4);
            float4 vb = *(const float4*)(smc + PRAW + (2 * d2 + 1) * 256 + eg * 4);
            float fa[4] = {va.x, va.y, va.z, va.w};
            float fb[4] = {vb.x, vb.y, vb.z, vb.w};
#pragma unroll
            for (int j = 0; j < 4; j++) {
                u32 h, l;
                packsplit(fa[j], fb[j], h, l);   // (w[d][e], w[d+1][e])
                u32 o = off64(eg + j, d2 * 4);
                *(u32*)(smc + PWH + o) = h;
                *(u32*)(smc + PWL + o) = l;
            }
        }
        __syncthreads();   // images ready; raw buffer free for prefetch

        // Prefetch raw W(ch+1) — overlaps the mma below.
        if (ch + 1 < 12) {
            const int pn = (ch + 1) >> 2;
            const int cn = ((ch + 1) & 3) << 6;
            const float* wsrc = w + (size_t)pn * ND * NE + cn;
            for (int i = tid; i < 4096; i += 512) {
                int d = i >> 4, seg = (i & 15) << 4;
                cp16(sm + PRAW + d * 256 + seg, (const char*)wsrc + (size_t)d * NE * 4 + seg);
            }
            cp_commit();
        }

        // ---- 3-split mma: 16 k-steps (xh*wh + xh*wl + xl*wh) ----
        float S0[4] = {0.f, 0.f, 0.f, 0.f}, S1[4] = {0.f, 0.f, 0.f, 0.f};
#pragma unroll
        for (int st = 0; st < 16; st++) {
            u32 ah[4], al[4], bh[4], bl[4];
            lda(ah, sm + PXH, r0, st * 32, lane, true);
            lda(al, sm + PXL, r0, st * 32, lane, true);
            ldb(bh, sm + PWH, n0, st * 32, lane, true);
            ldb(bl, sm + PWL, n0, st * 32, lane, true);
            mma_bf16(S0, ah, bh[0], bh[1]); mma_bf16(S1, ah, bh[2], bh[3]);
            mma_bf16(S0, ah, bl[0], bl[1]); mma_bf16(S1, ah, bl[2], bl[3]);
            mma_bf16(S0, al, bh[0], bh[1]); mma_bf16(S1, al, bh[2], bh[3]);
        }

        // ---- stage results in destination orientation ----
        if (p < 2) {
            // [row][col] orientation: staging row = X row, col = e local
            u32 h, l;
            packsplit(S0[0], S0[1], h, l);
            *(u32*)(smc + PSH + rl * 128 + c0 * 2) = h;
            *(u32*)(smc + PSL + rl * 128 + c0 * 2) = l;
            packsplit(S0[2], S0[3], h, l);
            *(u32*)(smc + PSH + rh * 128 + c0 * 2) = h;
            *(u32*)(smc + PSL + rh * 128 + c0 * 2) = l;
            packsplit(S1[0], S1[1], h, l);
            *(u32*)(smc + PSH + rl * 128 + (c0 + 8) * 2) = h;
            *(u32*)(smc + PSL + rl * 128 + (c0 + 8) * 2) = l;
            packsplit(S1[2], S1[3], h, l);
            *(u32*)(smc + PSH + rh * 128 + (c0 + 8) * 2) = h;
            *(u32*)(smc + PSL + rh * 128 + (c0 + 8) * 2) = l;
        } else {
            // V: staging row = e local, col = key local (transposed scatter)
            float vals[8] = {S0[0], S0[1], S0[2], S0[3], S1[0], S1[1], S1[2], S1[3]};
            int es[8]   = {c0, c0 + 1, c0, c0 + 1, c0 + 8, c0 + 9, c0 + 8, c0 + 9};
            int keys[8] = {rl, rl, rh, rh, rl, rl, rh, rh};
#pragma unroll
            for (int j = 0; j < 8; j++) {
                __nv_bfloat16 hb = __float2bfloat16_rn(vals[j]);
                __nv_bfloat16 lb = __float2bfloat16_rn(vals[j] - __bfloat162float(hb));
                *(u16*)(smc + PSH + es[j] * 128 + keys[j] * 2) = __bfloat16_as_ushort(hb);
                *(u16*)(smc + PSL + es[j] * 128 + keys[j] * 2) = __bfloat16_as_ushort(lb);
            }
        }
        __syncthreads();   // staging complete

        // ---- coalesced copy-out: 64 rows x 128B per array ----
        if (p < 2) {
            __nv_bfloat16* Gh = (p == 0) ? gQh : gKh;
            __nv_bfloat16* Gl = (p == 0) ? gQl : gKl;
            for (int i = tid; i < 1024; i += 512) {
                int arr = i >> 9, r = (i & 511) >> 3, cb = (i & 7) << 4;
                uint4 v = *(const uint4*)(smc + (arr ? PSL : PSH) + r * 128 + cb);
                __nv_bfloat16* G = arr ? Gl : Gh;
                *(uint4*)((char*)&G[(size_t)(rows0 + r) * NE + col0] + cb) = v;
            }
        } else {
            for (int i = tid; i < 1024; i += 512) {
                int arr = i >> 9, e = (i & 511) >> 3, kb = (i & 7) << 4;
                uint4 v = *(const uint4*)(smc + (arr ? PSL : PSH) + e * 128 + kb);
                __nv_bfloat16* G = arr ? gVtl : gVth;
                *(uint4*)((char*)&G[((size_t)b * NE + col0 + e) * NS + key0] + kb) = v;
            }
        }
        // next chunk-top __syncthreads protects staging reuse
    }
}

// ---------------------------------------------------------------------------
// Attention (UNCHANGED from R11): 64 q per block, 512 threads, single pass
// online softmax; 4-way split QK, 3-way split PV.
// ---------------------------------------------------------------------------
#define SM_RS   0
#define SM_RED  256
#define SM_QH   2048
#define SM_QL   (SM_QH + 32768)
#define SM_KH   (SM_QL + 32768)
#define SM_KL   (SM_KH + 32768)
#define SM_VH   (SM_KL + 32768)
#define SM_VL   (SM_VH + 32768)
#define SM_PH   (SM_VL + 32768)
#define SM_PL   (SM_PH + 8192)
#define SM_TOT  (SM_PL + 8192)

__device__ __forceinline__ void load64img(u32 base, const __nv_bfloat16* src, int tid) {
    for (int c = tid; c < 2048; c += 512) {
        int r = c >> 5, eb = (c & 31) << 4;
        cp16(base + off64(r, eb), (const char*)src + (size_t)r * 512 + eb);
    }
}
__device__ __forceinline__ void loadvt(u32 base, const __nv_bfloat16* src, int tid) {
    for (int c = tid; c < 2048; c += 512) {
        int e = c >> 3, kb = (c & 7) << 4;
        cp16(base + off128(e, kb), (const char*)src + (size_t)e * (NS * 2) + kb);
    }
}

__global__ __launch_bounds__(512, 1) void attn_mma(const int* __restrict__ mask,
                                                   float* __restrict__ out) {
    extern __shared__ __align__(1024) char smc[];
    const u32 sm = (u32)__cvta_generic_to_shared(smc);
    float* rs = (float*)(smc + SM_RS);
    float* red = (float*)(smc + SM_RED);

    const int b = blockIdx.y, q0 = blockIdx.x * 64;
    const int tid = threadIdx.x, lane = tid & 31, wid = tid >> 5;
    const int wq = wid & 3, wn = wid >> 2;
    const int r0 = wq * 16;
    const int rl = r0 + (lane >> 2), rh = rl + 8;
    const int n0 = wn * 16;
    const int e0 = wn * 64;

    const __nv_bfloat16* Qh_g = gQh + (size_t)(b * NS + q0) * NE;
    const __nv_bfloat16* Ql_g = gQl + (size_t)(b * NS + q0) * NE;
    const __nv_bfloat16* Kh_g = gKh + (size_t)b * NS * NE;
    const __nv_bfloat16* Kl_g = gKl + (size_t)b * NS * NE;
    const __nv_bfloat16* Vth_g = gVth + (size_t)b * NE * NS;
    const __nv_bfloat16* Vtl_g = gVtl + (size_t)b * NE * NS;

    if (tid < 64) rs[tid] = kScale * (float)mask[b * NS + q0 + tid];

    load64img(sm + SM_QH, Qh_g, tid);
    load64img(sm + SM_QL, Ql_g, tid);
    load64img(sm + SM_KH, Kh_g, tid);
    load64img(sm + SM_KL, Kl_g, tid);
    cp_commit();
    loadvt(sm + SM_VH, Vth_g, tid);
    loadvt(sm + SM_VL, Vtl_g, tid);
    cp_commit();
    __syncthreads();

    const float rsc_l = rs[rl], rsc_h = rs[rh];

    float O[8][4];
#pragma unroll
    for (int i = 0; i < 8; i++)
#pragma unroll
        for (int j = 0; j < 4; j++) O[i][j] = 0.f;
    float l_l = 0.f, l_h = 0.f;
    float m_l = -1e30f, m_h = -1e30f;

    for (int kt = 0; kt < 32; kt++) {
        cp_wait1();
        __syncthreads();

        float S0[4] = {0.f, 0.f, 0.f, 0.f}, S1[4] = {0.f, 0.f, 0.f, 0.f};
#pragma unroll
        for (int st = 0; st < 16; st++) {
            u32 ah[4], al[4], bh[4], bl[4];
            lda(ah, sm + SM_QH, r0, st * 32, lane, true);
            lda(al, sm + SM_QL, r0, st * 32, lane, true);
            ldb(bh, sm + SM_KH, n0, st * 32, lane, true);
            ldb(bl, sm + SM_KL, n0, st * 32, lane, true);
            mma_bf16(S0, ah, bh[0], bh[1]); mma_bf16(S1, ah, bh[2], bh[3]);
            mma_bf16(S0, ah, bl[0], bl[1]); mma_bf16(S1, ah, bl[2], bl[3]);
            mma_bf16(S0, al, bh[0], bh[1]); mma_bf16(S1, al, bh[2], bh[3]);
            mma_bf16(S0, al, bl[0], bl[1]); mma_bf16(S1, al, bl[2], bl[3]);
        }

        float wm_l = fmaxf(fmaxf(S0[0], S0[1]), fmaxf(S1[0], S1[1]));
        float wm_h = fmaxf(fmaxf(S0[2], S0[3]), fmaxf(S1[2], S1[3]));
        wm_l = fmaxf(wm_l, __shfl_xor_sync(~0u, wm_l, 1));
        wm_l = fmaxf(wm_l, __shfl_xor_sync(~0u, wm_l, 2));
        wm_h = fmaxf(wm_h, __shfl_xor_sync(~0u, wm_h, 1));
        wm_h = fmaxf(wm_h, __shfl_xor_sync(~0u, wm_h, 2));
        if ((lane & 3) == 0) { red[wn * 64 + rl] = wm_l; red[wn * 64 + rh] = wm_h; }
        __syncthreads();

        if (kt + 1 < 32) {
            load64img(sm + SM_KH, Kh_g + (size_t)(kt + 1) * 64 * NE, tid);
            load64img(sm + SM_KL, Kl_g + (size_t)(kt + 1) * 64 * NE, tid);
            cp_commit();
        }

        float nm_l = fmaxf(fmaxf(red[rl], red[64 + rl]),
                           fmaxf(red[128 + rl], red[192 + rl])) * rsc_l;
        float nm_h = fmaxf(fmaxf(red[rh], red[64 + rh]),
                           fmaxf(red[128 + rh], red[192 + rh])) * rsc_h;
        nm_l = fmaxf(m_l, nm_l);
        nm_h = fmaxf(m_h, nm_h);
        const float al_l = __expf(m_l - nm_l), al_h = __expf(m_h - nm_h);
        m_l = nm_l; m_h = nm_h;
#pragma unroll
        for (int nt = 0; nt < 8; nt++) {
            O[nt][0] *= al_l; O[nt][1] *= al_l;
            O[nt][2] *= al_h; O[nt][3] *= al_h;
        }

        {
            float p00 = __expf(S0[0] * rsc_l - m_l);
            float p01 = __expf(S0[1] * rsc_l - m_l);
            float p10 = __expf(S1[0] * rsc_l - m_l);
            float p11 = __expf(S1[1] * rsc_l - m_l);
            float q00 = __expf(S0[2] * rsc_h - m_h);
            float q01 = __expf(S0[3] * rsc_h - m_h);
            float q10 = __expf(S1[2] * rsc_h - m_h);
            float q11 = __expf(S1[3] * rsc_h - m_h);
            l_l = l_l * al_l + (p00 + p01 + p10 + p11);
            l_h = l_h * al_h + (q00 + q01 + q10 + q11);
            int cb = (n0 + 2 * (lane & 3)) * 2;
            u32 h0, l0, h1, l1, h2, l2, h3, l3;
            packsplit(p00, p01, h0, l0);
            packsplit(p10, p11, h1, l1);
            packsplit(q00, q01, h2, l2);
            packsplit(q10, q11, h3, l3);
            *(u32*)(smc + SM_PH + off128(rl, cb))      = h0;
            *(u32*)(smc + SM_PH + off128(rl, cb + 16)) = h1;
            *(u32*)(smc + SM_PH + off128(rh, cb))      = h2;
            *(u32*)(smc + SM_PH + off128(rh, cb + 16)) = h3;
            *(u32*)(smc + SM_PL + off128(rl, cb))      = l0;
            *(u32*)(smc + SM_PL + off128(rl, cb + 16)) = l1;
            *(u32*)(smc + SM_PL + off128(rh, cb))      = l2;
            *(u32*)(smc + SM_PL + off128(rh, cb + 16)) = l3;
        }

        if (kt == 31) cp_wait0(); else cp_wait1();
        __syncthreads();

#pragma unroll
        for (int kk = 0; kk < 4; kk++) {
            u32 ph[4], pl[4];
            lda(ph, sm + SM_PH, r0, kk * 32, lane, false);
            lda(pl, sm + SM_PL, r0, kk * 32, lane, false);
#pragma unroll
            for (int np = 0; np < 4; np++) {
                u32 vh[4], vl[4];
                ldb(vh, sm + SM_VH, e0 + np * 16, kk * 32, lane, false);
                ldb(vl, sm + SM_VL, e0 + np * 16, kk * 32, lane, false);
                mma_bf16(O[np * 2],     ph, vh[0], vh[1]);
                mma_bf16(O[np * 2 + 1], ph, vh[2], vh[3]);
                mma_bf16(O[np * 2],     ph, vl[0], vl[1]);
                mma_bf16(O[np * 2 + 1], ph, vl[2], vl[3]);
                mma_bf16(O[np * 2],     pl, vh[0], vh[1]);
                mma_bf16(O[np * 2 + 1], pl, vh[2], vh[3]);
            }
        }
        __syncthreads();

        if (kt + 1 < 32) {
            loadvt(sm + SM_VH, Vth_g + (size_t)(kt + 1) * 64, tid);
            loadvt(sm + SM_VL, Vtl_g + (size_t)(kt + 1) * 64, tid);
            cp_commit();
        }
    }

    l_l += __shfl_xor_sync(~0u, l_l, 1);
    l_l += __shfl_xor_sync(~0u, l_l, 2);
    l_h += __shfl_xor_sync(~0u, l_h, 1);
    l_h += __shfl_xor_sync(~0u, l_h, 2);
    if ((lane & 3) == 0) { red[wn * 64 + rl] = l_l; red[wn * 64 + rh] = l_h; }
    __syncthreads();
    const float inv_l = 1.0f / (red[rl] + red[64 + rl] + red[128 + rl] + red[192 + rl]);
    const float inv_h = 1.0f / (red[rh] + red[64 + rh] + red[128 + rh] + red[192 + rh]);

    float* orow_l = out + (size_t)(b * NS + q0 + rl) * NE;
    float* orow_h = out + (size_t)(b * NS + q0 + rh) * NE;
#pragma unroll
    for (int nt = 0; nt < 8; nt++) {
        int col = e0 + nt * 8 + 2 * (lane & 3);
        *(float2*)&orow_l[col] = make_float2(O[nt][0] * inv_l, O[nt][1] * inv_l);
        *(float2*)&orow_h[col] = make_float2(O[nt][2] * inv_h, O[nt][3] * inv_h);
    }
}

// ---------------------------------------------------------------------------
extern "C" void kernel_launch(void* const* d_in, const int* in_sizes, int n_in,
                              void* d_out, int out_size) {
    (void)in_sizes; (void)n_in; (void)out_size;
    const float* x    = (const float*)d_in[0];
    const float* w    = (const float*)d_in[1];
    const int*   mask = (const int*)d_in[2];
    float* out = (float*)d_out;

    cudaFuncSetAttribute(qkv_prep5, cudaFuncAttributeMaxDynamicSharedMemorySize, PTOT);
    qkv_prep5<<<(NB * NS) / 64, 512, PTOT>>>(x, w);

    cudaFuncSetAttribute(attn_mma, cudaFuncAttributeMaxDynamicSharedMemorySize, SM_TOT);
    dim3 g2(NS / 64, NB);
    attn_mma<<<g2, 512, SM_TOT>>>(mask, out);
}

// round 17
// speedup vs baseline: 1.1074x; 1.1074x over previous
#include <cuda_runtime.h>
#include <cuda_bf16.h>
#include <math.h>
#include <stdint.h>

#define NB 8
#define NS 2048
#define ND 256
#define NE 256
static constexpr float kScale = 0.125f;  // 1/sqrt(64), per reference source

typedef unsigned long long u64;
typedef uint32_t u32;
typedef unsigned short u16;

// ---------------- cp.async ----------------
__device__ __forceinline__ void cp16(u32 smem_dst, const void* gmem_src) {
    asm volatile("cp.async.cg.shared.global [%0], [%1], 16;" :: "r"(smem_dst), "l"(gmem_src));
}
__device__ __forceinline__ void cp_commit() {
    asm volatile("cp.async.commit_group;" ::: "memory");
}
__device__ __forceinline__ void cp_wait0() { asm volatile("cp.async.wait_group 0;" ::: "memory"); }
__device__ __forceinline__ void cp_wait1() { asm volatile("cp.async.wait_group 1;" ::: "memory"); }

// ---------------- mma.sync / ldmatrix (family-wide, works on sm_103) ----------
__device__ __forceinline__ void ldsm4(u32* d, u32 addr) {
    asm volatile("ldmatrix.sync.aligned.m8n8.x4.shared.b16 {%0,%1,%2,%3}, [%4];"
        : "=r"(d[0]), "=r"(d[1]), "=r"(d[2]), "=r"(d[3]) : "r"(addr));
}
__device__ __forceinline__ void mma_bf16(float* c, const u32* a, u32 b0, u32 b1) {
    asm volatile("mma.sync.aligned.m16n8k16.row.col.f32.bf16.bf16.f32 "
        "{%0,%1,%2,%3}, {%4,%5,%6,%7}, {%8,%9}, {%0,%1,%2,%3};"
        : "+f"(c[0]), "+f"(c[1]), "+f"(c[2]), "+f"(c[3])
        : "r"(a[0]), "r"(a[1]), "r"(a[2]), "r"(a[3]), "r"(b0), "r"(b1));
}

// ---------------- shared helpers ----------------
__device__ __forceinline__ u32 swz(u32 o) { return o ^ ((o >> 3) & 0x70); }
// 64-row x 512B image in 1KB atoms (8 rows x 128B), atom = (r>>3) + (cb>>7)*8
__device__ __forceinline__ u32 off64(int r, int cb) {
    return swz((u32)(((r >> 3) + (cb >> 7) * 8) * 1024 + (r & 7) * 128 + (cb & 127)));
}
// 128B-row image (Vt: 256 rows, P: 64 rows)
__device__ __forceinline__ u32 off128(int r, int cb) {
    return swz((u32)(r * 128 + cb));
}
// A-fragment (m16k16): reg g -> rows r0+8*(g&1), col cb+16*(g>>1)
__device__ __forceinline__ void lda(u32* d, u32 base, int r0, int cb, int lane, bool wide) {
    int g = lane >> 3;
    int r = r0 + (lane & 7) + (g & 1) * 8;
    int c = cb + (g >> 1) * 16;
    ldsm4(d, base + (wide ? off64(r, c) : off128(r, c)));
}
// B-fragments for two n-tiles: reg g -> rows n0+8*(g>>1), col cb+16*(g&1)
__device__ __forceinline__ void ldb(u32* d, u32 base, int n0, int cb, int lane, bool wide) {
    int g = lane >> 3;
    int r = n0 + (lane & 7) + (g >> 1) * 8;
    int c = cb + (g & 1) * 16;
    ldsm4(d, base + (wide ? off64(r, c) : off128(r, c)));
}

__device__ __forceinline__ void packsplit(float x, float y, u32& hi, u32& lo) {
    __nv_bfloat16 xh = __float2bfloat16_rn(x), yh = __float2bfloat16_rn(y);
    __nv_bfloat16 xl = __float2bfloat16_rn(x - __bfloat162float(xh));
    __nv_bfloat16 yl = __float2bfloat16_rn(y - __bfloat162float(yh));
    hi = (u32)__bfloat16_as_ushort(xh) | ((u32)__bfloat16_as_ushort(yh) << 16);
    lo = (u32)__bfloat16_as_ushort(xl) | ((u32)__bfloat16_as_ushort(yl) << 16);
}

// ---------------- global bf16 scratch ----------------
__device__ __align__(16) __nv_bfloat16 gQh[NB * NS * NE];
__device__ __align__(16) __nv_bfloat16 gQl[NB * NS * NE];
__device__ __align__(16) __nv_bfloat16 gKh[NB * NS * NE];
__device__ __align__(16) __nv_bfloat16 gKl[NB * NS * NE];
__device__ __align__(16) __nv_bfloat16 gVth[NB * NE * NS];
__device__ __align__(16) __nv_bfloat16 gVtl[NB * NE * NS];
// Pre-swizzled W hi/lo images: 12 chunks (p*4 + colchunk) x 32KB each
__device__ __align__(16) char gWih[12 * 32768];
__device__ __align__(16) char gWil[12 * 32768];

// ---------------------------------------------------------------------------
// Kernel 0: build W hi/lo SW128 images ONCE. 12 blocks, one per
// (projection, col-chunk).
// ---------------------------------------------------------------------------
__global__ __launch_bounds__(256) void w_image(const float* __restrict__ w) {
    const int ch = blockIdx.x;
    const int p = ch >> 2;
    const int col0 = (ch & 3) << 6;
    const int tid = threadIdx.x;
    char* dh = gWih + (size_t)ch * 32768;
    char* dl = gWil + (size_t)ch * 32768;

    for (int i = tid; i < 2048; i += 256) {
        int d2 = i >> 4;
        int eg = (i & 15) << 2;
        const float* wp = w + (size_t)p * ND * NE + (size_t)(2 * d2) * NE + col0 + eg;
        float4 va = *(const float4*)wp;
        float4 vb = *(const float4*)(wp + NE);
        float fa[4] = {va.x, va.y, va.z, va.w};
        float fb[4] = {vb.x, vb.y, vb.z, vb.w};
#pragma unroll
        for (int j = 0; j < 4; j++) {
            u32 h, l;
            packsplit(fa[j], fb[j], h, l);   // (w[d][e], w[d+1][e])
            u32 o = off64(eg + j, d2 * 4);
            *(u32*)(dh + o) = h;
            *(u32*)(dl + o) = l;
        }
    }
}

// ---------------------------------------------------------------------------
// Prep v6b: per-block critical path = X fill + 12 x (mma + epilogue).
// W images pre-built; streamed via coalesced cp.async, double-buffered.
// FIX vs R16: prefetch loops copy the FULL 64KB (hi 32KB + lo 32KB):
// 4096 iterations, half = i>>11, off = (i&2047)<<4.
// ---------------------------------------------------------------------------
#define PXH   0
#define PXL   32768
#define PW0H  65536
#define PW0L  98304
#define PW1H  131072
#define PW1L  163840
#define PSH   196608          // staging hi: [64][64] bf16 (8KB)
#define PSL   204800          // staging lo: [64][64] bf16 (8KB)
#define PTOT  212992

__global__ __launch_bounds__(512, 1) void qkv_prep6(const float* __restrict__ x) {
    extern __shared__ __align__(1024) char smc[];
    const u32 sm = (u32)__cvta_generic_to_shared(smc);
    const int rows0 = blockIdx.x * 64;
    const int b = rows0 >> 11;
    const int key0 = rows0 & (NS - 1);
    const int tid = threadIdx.x, lane = tid & 31, wid = tid >> 5;
    const int wq = wid & 3, wn = wid >> 2;
    const int r0 = wq * 16, n0 = wn * 16;
    const int rl = r0 + (lane >> 2), rh = rl + 8;
    const int c0 = n0 + 2 * (lane & 3);

    // ---- prefetch W image(0) into buffer 0 (full 64KB: hi + lo) ----
    for (int i = tid; i < 4096; i += 512) {
        int half = i >> 11, off = (i & 2047) << 4;
        cp16(sm + (half ? PW0L : PW0H) + off, (half ? gWil : gWih) + off);
    }
    cp_commit();

    // ---- X tile 64x256 fp32 -> Xh/Xl images, ONCE ----
    for (int i = tid; i < 4096; i += 512) {
        int r = i >> 6, d0 = (i & 63) << 2;
        float4 v = *(const float4*)&x[(size_t)(rows0 + r) * ND + d0];
        u32 h0, l0, h1, l1;
        packsplit(v.x, v.y, h0, l0);
        packsplit(v.z, v.w, h1, l1);
        u32 o = off64(r, d0 * 2);
        *(uint2*)(smc + PXH + o) = make_uint2(h0, h1);
        *(uint2*)(smc + PXL + o) = make_uint2(l0, l1);
    }

    // ---- 12 chunks: p = ch/4, col0 = (ch%4)*64; double-buffered W images ----
    for (int ch = 0; ch < 12; ch++) {
        const int p = ch >> 2;
        const int col0 = (ch & 3) << 6;
        const u32 wbh = (ch & 1) ? PW1H : PW0H;
        const u32 wbl = (ch & 1) ? PW1L : PW0L;

        cp_wait0();        // W(ch) image resident (thread-local parts)
        __syncthreads();   // all parts visible; X ready; staging drained

        // prefetch W(ch+1) into the other buffer — overlaps the mma below
        if (ch + 1 < 12) {
            const u32 nbh = (ch & 1) ? PW0H : PW1H;
            const u32 nbl = (ch & 1) ? PW0L : PW1L;
            const char* sh = gWih + (size_t)(ch + 1) * 32768;
            const char* sl = gWil + (size_t)(ch + 1) * 32768;
            for (int i = tid; i < 4096; i += 512) {
                int half = i >> 11, off = (i & 2047) << 4;
                cp16(sm + (half ? nbl : nbh) + off, (half ? sl : sh) + off);
            }
            cp_commit();
        }

        // ---- 3-split mma: 16 k-steps (xh*wh + xh*wl + xl*wh) ----
        float S0[4] = {0.f, 0.f, 0.f, 0.f}, S1[4] = {0.f, 0.f, 0.f, 0.f};
#pragma unroll
        for (int st = 0; st < 16; st++) {
            u32 ah[4], al[4], bh[4], bl[4];
            lda(ah, sm + PXH, r0, st * 32, lane, true);
            lda(al, sm + PXL, r0, st * 32, lane, true);
            ldb(bh, sm + wbh, n0, st * 32, lane, true);
            ldb(bl, sm + wbl, n0, st * 32, lane, true);
            mma_bf16(S0, ah, bh[0], bh[1]); mma_bf16(S1, ah, bh[2], bh[3]);
            mma_bf16(S0, ah, bl[0], bl[1]); mma_bf16(S1, ah, bl[2], bl[3]);
            mma_bf16(S0, al, bh[0], bh[1]); mma_bf16(S1, al, bh[2], bh[3]);
        }

        // ---- stage results in destination orientation ----
        if (p < 2) {
            u32 h, l;
            packsplit(S0[0], S0[1], h, l);
            *(u32*)(smc + PSH + rl * 128 + c0 * 2) = h;
            *(u32*)(smc + PSL + rl * 128 + c0 * 2) = l;
            packsplit(S0[2], S0[3], h, l);
            *(u32*)(smc + PSH + rh * 128 + c0 * 2) = h;
            *(u32*)(smc + PSL + rh * 128 + c0 * 2) = l;
            packsplit(S1[0], S1[1], h, l);
            *(u32*)(smc + PSH + rl * 128 + (c0 + 8) * 2) = h;
            *(u32*)(smc + PSL + rl * 128 + (c0 + 8) * 2) = l;
            packsplit(S1[2], S1[3], h, l);
            *(u32*)(smc + PSH + rh * 128 + (c0 + 8) * 2) = h;
            *(u32*)(smc + PSL + rh * 128 + (c0 + 8) * 2) = l;
        } else {
            float vals[8] = {S0[0], S0[1], S0[2], S0[3], S1[0], S1[1], S1[2], S1[3]};
            int es[8]   = {c0, c0 + 1, c0, c0 + 1, c0 + 8, c0 + 9, c0 + 8, c0 + 9};
            int keys[8] = {rl, rl, rh, rh, rl, rl, rh, rh};
#pragma unroll
            for (int j = 0; j < 8; j++) {
                __nv_bfloat16 hb = __float2bfloat16_rn(vals[j]);
                __nv_bfloat16 lb = __float2bfloat16_rn(vals[j] - __bfloat162float(hb));
                *(u16*)(smc + PSH + es[j] * 128 + keys[j] * 2) = __bfloat16_as_ushort(hb);
                *(u16*)(smc + PSL + es[j] * 128 + keys[j] * 2) = __bfloat16_as_ushort(lb);
            }
        }
        __syncthreads();   // staging complete

        // ---- coalesced copy-out: 64 rows x 128B per array ----
        if (p < 2) {
            __nv_bfloat16* Gh = (p == 0) ? gQh : gKh;
            __nv_bfloat16* Gl = (p == 0) ? gQl : gKl;
            for (int i = tid; i < 1024; i += 512) {
                int arr = i >> 9, r = (i & 511) >> 3, cb = (i & 7) << 4;
                uint4 v = *(const uint4*)(smc + (arr ? PSL : PSH) + r * 128 + cb);
                __nv_bfloat16* G = arr ? Gl : Gh;
                *(uint4*)((char*)&G[(size_t)(rows0 + r) * NE + col0] + cb) = v;
            }
        } else {
            for (int i = tid; i < 1024; i += 512) {
                int arr = i >> 9, e = (i & 511) >> 3, kb = (i & 7) << 4;
                uint4 v = *(const uint4*)(smc + (arr ? PSL : PSH) + e * 128 + kb);
                __nv_bfloat16* G = arr ? gVtl : gVth;
                *(uint4*)((char*)&G[((size_t)b * NE + col0 + e) * NS + key0] + kb) = v;
            }
        }
        // next chunk-top __syncthreads protects staging + image-buffer reuse
    }
}

// ---------------------------------------------------------------------------
// Attention (UNCHANGED from R11): 64 q per block, 512 threads, single pass
// online softmax; 4-way split QK, 3-way split PV.
// ---------------------------------------------------------------------------
#define SM_RS   0
#define SM_RED  256
#define SM_QH   2048
#define SM_QL   (SM_QH + 32768)
#define SM_KH   (SM_QL + 32768)
#define SM_KL   (SM_KH + 32768)
#define SM_VH   (SM_KL + 32768)
#define SM_VL   (SM_VH + 32768)
#define SM_PH   (SM_VL + 32768)
#define SM_PL   (SM_PH + 8192)
#define SM_TOT  (SM_PL + 8192)

__device__ __forceinline__ void load64img(u32 base, const __nv_bfloat16* src, int tid) {
    for (int c = tid; c < 2048; c += 512) {
        int r = c >> 5, eb = (c & 31) << 4;
        cp16(base + off64(r, eb), (const char*)src + (size_t)r * 512 + eb);
    }
}
__device__ __forceinline__ void loadvt(u32 base, const __nv_bfloat16* src, int tid) {
    for (int c = tid; c < 2048; c += 512) {
        int e = c >> 3, kb = (c & 7) << 4;
        cp16(base + off128(e, kb), (const char*)src + (size_t)e * (NS * 2) + kb);
    }
}

__global__ __launch_bounds__(512, 1) void attn_mma(const int* __restrict__ mask,
                                                   float* __restrict__ out) {
    extern __shared__ __align__(1024) char smc[];
    const u32 sm = (u32)__cvta_generic_to_shared(smc);
    float* rs = (float*)(smc + SM_RS);
    float* red = (float*)(smc + SM_RED);

    const int b = blockIdx.y, q0 = blockIdx.x * 64;
    const int tid = threadIdx.x, lane = tid & 31, wid = tid >> 5;
    const int wq = wid & 3, wn = wid >> 2;
    const int r0 = wq * 16;
    const int rl = r0 + (lane >> 2), rh = rl + 8;
    const int n0 = wn * 16;
    const int e0 = wn * 64;

    const __nv_bfloat16* Qh_g = gQh + (size_t)(b * NS + q0) * NE;
    const __nv_bfloat16* Ql_g = gQl + (size_t)(b * NS + q0) * NE;
    const __nv_bfloat16* Kh_g = gKh + (size_t)b * NS * NE;
    const __nv_bfloat16* Kl_g = gKl + (size_t)b * NS * NE;
    const __nv_bfloat16* Vth_g = gVth + (size_t)b * NE * NS;
    const __nv_bfloat16* Vtl_g = gVtl + (size_t)b * NE * NS;

    if (tid < 64) rs[tid] = kScale * (float)mask[b * NS + q0 + tid];

    load64img(sm + SM_QH, Qh_g, tid);
    load64img(sm + SM_QL, Ql_g, tid);
    load64img(sm + SM_KH, Kh_g, tid);
    load64img(sm + SM_KL, Kl_g, tid);
    cp_commit();
    loadvt(sm + SM_VH, Vth_g, tid);
    loadvt(sm + SM_VL, Vtl_g, tid);
    cp_commit();
    __syncthreads();

    const float rsc_l = rs[rl], rsc_h = rs[rh];

    float O[8][4];
#pragma unroll
    for (int i = 0; i < 8; i++)
#pragma unroll
        for (int j = 0; j < 4; j++) O[i][j] = 0.f;
    float l_l = 0.f, l_h = 0.f;
    float m_l = -1e30f, m_h = -1e30f;

    for (int kt = 0; kt < 32; kt++) {
        cp_wait1();
        __syncthreads();

        float S0[4] = {0.f, 0.f, 0.f, 0.f}, S1[4] = {0.f, 0.f, 0.f, 0.f};
#pragma unroll
        for (int st = 0; st < 16; st++) {
            u32 ah[4], al[4], bh[4], bl[4];
            lda(ah, sm + SM_QH, r0, st * 32, lane, true);
            lda(al, sm + SM_QL, r0, st * 32, lane, true);
            ldb(bh, sm + SM_KH, n0, st * 32, lane, true);
            ldb(bl, sm + SM_KL, n0, st * 32, lane, true);
            mma_bf16(S0, ah, bh[0], bh[1]); mma_bf16(S1, ah, bh[2], bh[3]);
            mma_bf16(S0, ah, bl[0], bl[1]); mma_bf16(S1, ah, bl[2], bl[3]);
            mma_bf16(S0, al, bh[0], bh[1]); mma_bf16(S1, al, bh[2], bh[3]);
            mma_bf16(S0, al, bl[0], bl[1]); mma_bf16(S1, al, bl[2], bl[3]);
        }

        float wm_l = fmaxf(fmaxf(S0[0], S0[1]), fmaxf(S1[0], S1[1]));
        float wm_h = fmaxf(fmaxf(S0[2], S0[3]), fmaxf(S1[2], S1[3]));
        wm_l = fmaxf(wm_l, __shfl_xor_sync(~0u, wm_l, 1));
        wm_l = fmaxf(wm_l, __shfl_xor_sync(~0u, wm_l, 2));
        wm_h = fmaxf(wm_h, __shfl_xor_sync(~0u, wm_h, 1));
        wm_h = fmaxf(wm_h, __shfl_xor_sync(~0u, wm_h, 2));
        if ((lane & 3) == 0) { red[wn * 64 + rl] = wm_l; red[wn * 64 + rh] = wm_h; }
        __syncthreads();

        if (kt + 1 < 32) {
            load64img(sm + SM_KH, Kh_g + (size_t)(kt + 1) * 64 * NE, tid);
            load64img(sm + SM_KL, Kl_g + (size_t)(kt + 1) * 64 * NE, tid);
            cp_commit();
        }

        float nm_l = fmaxf(fmaxf(red[rl], red[64 + rl]),
                           fmaxf(red[128 + rl], red[192 + rl])) * rsc_l;
        float nm_h = fmaxf(fmaxf(red[rh], red[64 + rh]),
                           fmaxf(red[128 + rh], red[192 + rh])) * rsc_h;
        nm_l = fmaxf(m_l, nm_l);
        nm_h = fmaxf(m_h, nm_h);
        const float al_l = __expf(m_l - nm_l), al_h = __expf(m_h - nm_h);
        m_l = nm_l; m_h = nm_h;
#pragma unroll
        for (int nt = 0; nt < 8; nt++) {
            O[nt][0] *= al_l; O[nt][1] *= al_l;
            O[nt][2] *= al_h; O[nt][3] *= al_h;
        }

        {
            float p00 = __expf(S0[0] * rsc_l - m_l);
            float p01 = __expf(S0[1] * rsc_l - m_l);
            float p10 = __expf(S1[0] * rsc_l - m_l);
            float p11 = __expf(S1[1] * rsc_l - m_l);
            float q00 = __expf(S0[2] * rsc_h - m_h);
            float q01 = __expf(S0[3] * rsc_h - m_h);
            float q10 = __expf(S1[2] * rsc_h - m_h);
            float q11 = __expf(S1[3] * rsc_h - m_h);
            l_l = l_l * al_l + (p00 + p01 + p10 + p11);
            l_h = l_h * al_h + (q00 + q01 + q10 + q11);
            int cb = (n0 + 2 * (lane & 3)) * 2;
            u32 h0, l0, h1, l1, h2, l2, h3, l3;
            packsplit(p00, p01, h0, l0);
            packsplit(p10, p11, h1, l1);
            packsplit(q00, q01, h2, l2);
            packsplit(q10, q11, h3, l3);
            *(u32*)(smc + SM_PH + off128(rl, cb))      = h0;
            *(u32*)(smc + SM_PH + off128(rl, cb + 16)) = h1;
            *(u32*)(smc + SM_PH + off128(rh, cb))      = h2;
            *(u32*)(smc + SM_PH + off128(rh, cb + 16)) = h3;
            *(u32*)(smc + SM_PL + off128(rl, cb))      = l0;
            *(u32*)(smc + SM_PL + off128(rl, cb + 16)) = l1;
            *(u32*)(smc + SM_PL + off128(rh, cb))      = l2;
            *(u32*)(smc + SM_PL + off128(rh, cb + 16)) = l3;
        }

        if (kt == 31) cp_wait0(); else cp_wait1();
        __syncthreads();

#pragma unroll
        for (int kk = 0; kk < 4; kk++) {
            u32 ph[4], pl[4];
            lda(ph, sm + SM_PH, r0, kk * 32, lane, false);
            lda(pl, sm + SM_PL, r0, kk * 32, lane, false);
#pragma unroll
            for (int np = 0; np < 4; np++) {
                u32 vh[4], vl[4];
                ldb(vh, sm + SM_VH, e0 + np * 16, kk * 32, lane, false);
                ldb(vl, sm + SM_VL, e0 + np * 16, kk * 32, lane, false);
                mma_bf16(O[np * 2],     ph, vh[0], vh[1]);
                mma_bf16(O[np * 2 + 1], ph, vh[2], vh[3]);
                mma_bf16(O[np * 2],     ph, vl[0], vl[1]);
                mma_bf16(O[np * 2 + 1], ph, vl[2], vl[3]);
                mma_bf16(O[np * 2],     pl, vh[0], vh[1]);
                mma_bf16(O[np * 2 + 1], pl, vh[2], vh[3]);
            }
        }
        __syncthreads();

        if (kt + 1 < 32) {
            loadvt(sm + SM_VH, Vth_g + (size_t)(kt + 1) * 64, tid);
            loadvt(sm + SM_VL, Vtl_g + (size_t)(kt + 1) * 64, tid);
            cp_commit();
        }
    }

    l_l += __shfl_xor_sync(~0u, l_l, 1);
    l_l += __shfl_xor_sync(~0u, l_l, 2);
    l_h += __shfl_xor_sync(~0u, l_h, 1);
    l_h += __shfl_xor_sync(~0u, l_h, 2);
    if ((lane & 3) == 0) { red[wn * 64 + rl] = l_l; red[wn * 64 + rh] = l_h; }
    __syncthreads();
    const float inv_l = 1.0f / (red[rl] + red[64 + rl] + red[128 + rl] + red[192 + rl]);
    const float inv_h = 1.0f / (red[rh] + red[64 + rh] + red[128 + rh] + red[192 + rh]);

    float* orow_l = out + (size_t)(b * NS + q0 + rl) * NE;
    float* orow_h = out + (size_t)(b * NS + q0 + rh) * NE;
#pragma unroll
    for (int nt = 0; nt < 8; nt++) {
        int col = e0 + nt * 8 + 2 * (lane & 3);
        *(float2*)&orow_l[col] = make_float2(O[nt][0] * inv_l, O[nt][1] * inv_l);
        *(float2*)&orow_h[col] = make_float2(O[nt][2] * inv_h, O[nt][3] * inv_h);
    }
}

// ---------------------------------------------------------------------------
extern "C" void kernel_launch(void* const* d_in, const int* in_sizes, int n_in,
                              void* d_out, int out_size) {
    (void)in_sizes; (void)n_in; (void)out_size;
    const float* x    = (const float*)d_in[0];
    const float* w    = (const float*)d_in[1];
    const int*   mask = (const int*)d_in[2];
    float* out = (float*)d_out;

    w_image<<<12, 256>>>(w);

    cudaFuncSetAttribute(qkv_prep6, cudaFuncAttributeMaxDynamicSharedMemorySize, PTOT);
    qkv_prep6<<<(NB * NS) / 64, 512, PTOT>>>(x);

    cudaFuncSetAttribute(attn_mma, cudaFuncAttributeMaxDynamicSharedMemorySize, SM_TOT);
    dim3 g2(NS / 64, NB);
    attn_mma<<<g2, 512, SM_TOT>>>(mask, out);
}